// round 8
// baseline (speedup 1.0000x reference)
#include <cuda_runtime.h>
#include <cstdint>

#define Bn   16
#define Tn   32
#define INn  112
#define Hn   512
#define NGn  7
#define En   409      // int(0.8*512)
#define EXn  410      // H - round(0.2*512)
#define AWc   0.02f
#define OMAWc 0.98f
#define AXc   0.2f
#define OMAXc 0.8f
#define DTc   0.02f
#define NT   1024

struct __align__(16) SM {
    float awbh[64 * Hn];    // alpha_w * relu(w_h2h) rows of this CTA   131072 B
    float wx[64 * INn];     // plastic input weights (thread-private)    28672 B
    float awbx[64 * INn];   // alpha_w * relu(w_x2h)                     28672 B
    float wa[NGn * Hn];     // plastic attn weights                      14336 B
    float awba[NGn * Hn];   //                                           14336 B
    float effc[Hn];         // relu(w_h2o[rank]) * exist                  2048 B
    float effv[Hn];         // relu(w_h2v) * exist                        2048 B
    float o[4][Hn];         // out(tau) lives in o[tau & 3]               8192 B
    float rowdat[64 * 4];   // per local row: {bh, awbd, wd, pad}         1024 B
    float logits4[4][8];
    float battn[8];
    float Rs[Tn];
};

__device__ __forceinline__ float warp_sum(float v) {
    v += __shfl_xor_sync(0xffffffffu, v, 16);
    v += __shfl_xor_sync(0xffffffffu, v, 8);
    v += __shfl_xor_sync(0xffffffffu, v, 4);
    v += __shfl_xor_sync(0xffffffffu, v, 2);
    v += __shfl_xor_sync(0xffffffffu, v, 1);
    return v;
}
__device__ __forceinline__ unsigned int smem_u32(const void* p) {
    unsigned int a;
    asm("{ .reg .u64 t; cvta.to.shared.u64 t, %1; cvt.u32.u64 %0, t; }" : "=r"(a) : "l"(p));
    return a;
}
__device__ __forceinline__ void st_clu(unsigned int laddr, int rank, float v) {
    unsigned int ra;
    asm volatile("mapa.shared::cluster.u32 %0, %1, %2;" : "=r"(ra) : "r"(laddr), "r"(rank));
    asm volatile("st.shared::cluster.f32 [%0], %1;" :: "r"(ra), "f"(v) : "memory");
}
// tanh(relu(x)) with fast exp/div; exact saturation beyond 15
__device__ __forceinline__ float tanh_relu_fast(float x) {
    float xr = fminf(fmaxf(x, 0.f), 15.f);
    float e2 = __expf(2.f * xr);
    return __fdividef(e2 - 1.f, e2 + 1.f);
}

__global__ void __launch_bounds__(NT, 1) __cluster_dims__(8, 1, 1)
rnn_kernel(const float* __restrict__ x, const float* __restrict__ R,
           const float* __restrict__ w_x2h, const float* __restrict__ w_h2h,
           const float* __restrict__ b_h2h, const float* __restrict__ w_attn,
           const float* __restrict__ b_attn, const float* __restrict__ w_h2o,
           const float* __restrict__ w_h2v, const float* __restrict__ kappa,
           float* __restrict__ yout)
{
    extern __shared__ __align__(16) char smraw[];
    SM& s = *reinterpret_cast<SM*>(smraw);

    const int tid  = threadIdx.x;
    const int w    = tid >> 5;          // 0..31
    const int l    = tid & 31;
    const int rank = blockIdx.x & 7;
    const int b    = blockIdx.x >> 3;
    const int rl0  = w * 2;             // local row base (0..62), 2 rows per warp
    const int row0 = rank * 64 + rl0;   // global row base
    const int lk   = l * 4;             // column base within a 128-block
    const int g    = w >> 2;            // attention group for warps < 28
    const int q    = w & 3;             // quarter-H slice for phase 1

    // ---------------- init ----------------
    if (tid < 8)  s.battn[tid] = (tid < NGn) ? b_attn[tid] : 0.f;
    if (tid < Tn) s.Rs[tid]    = R[tid * Bn + b];
    if (tid < Hn) {
        s.o[3][tid] = 0.f;              // out(-1) = 0
        s.effc[tid] = (tid < EXn) ? fmaxf(w_h2o[rank * Hn + tid], 0.f) : 0.f;
        s.effv[tid] = (tid < EXn) ? fmaxf(w_h2v[tid], 0.f) : 0.f;
    }
    for (int i = tid; i < NGn * Hn; i += NT) {
        float v = fmaxf(w_attn[i], 0.f);
        s.wa[i] = v; s.awba[i] = AWc * v;
    }
    if (l < 2) {
        const int row = row0 + l;
        const float dv = fmaxf(w_h2h[row * Hn + row], 0.f);
        s.rowdat[(rl0 + l) * 4 + 0] = b_h2h[row];
        s.rowdat[(rl0 + l) * 4 + 1] = AWc * dv;
        s.rowdat[(rl0 + l) * 4 + 2] = dv;
        s.rowdat[(rl0 + l) * 4 + 3] = 0.f;
    }

    // uniform kappa scalars
    const float k00 = kappa[0], k01 = kappa[1], k10 = kappa[2], k11 = kappa[3];
    const float kinAt = kappa[4 + 2 * (l >> 2)];
    const float kinBt = kappa[5 + 2 * (l >> 2)];
    const float kfb = (w < 28) ? kappa[18 + g / 3] : 0.f;

    float wh[2][16];
    #pragma unroll
    for (int r = 0; r < 2; r++) {
        const int row = row0 + r;
        #pragma unroll
        for (int c4 = 0; c4 < 4; c4++) {
            const int j0 = c4 * 128 + lk;
            float4 v = *reinterpret_cast<const float4*>(&w_h2h[row * Hn + j0]);
            v.x = fmaxf(v.x, 0.f); v.y = fmaxf(v.y, 0.f);
            v.z = fmaxf(v.z, 0.f); v.w = fmaxf(v.w, 0.f);
            wh[r][c4*4+0] = v.x; wh[r][c4*4+1] = v.y;
            wh[r][c4*4+2] = v.z; wh[r][c4*4+3] = v.w;
            *reinterpret_cast<float4*>(&s.awbh[(rl0 + r) * Hn + j0]) =
                make_float4(AWc*v.x, AWc*v.y, AWc*v.z, AWc*v.w);
        }
        if (l < 28) {
            float4 v = *reinterpret_cast<const float4*>(&w_x2h[row * INn + lk]);
            v.x = fmaxf(v.x, 0.f); v.y = fmaxf(v.y, 0.f);
            v.z = fmaxf(v.z, 0.f); v.w = fmaxf(v.w, 0.f);
            *reinterpret_cast<float4*>(&s.wx[(rl0 + r) * INn + lk]) = v;
            *reinterpret_cast<float4*>(&s.awbx[(rl0 + r) * INn + lk]) =
                make_float4(AWc*v.x, AWc*v.y, AWc*v.z, AWc*v.w);
        }
    }

    float state[2] = {0.f, 0.f};
    float attn_g = 0.f;

    __syncthreads();
    asm volatile("barrier.cluster.arrive.aligned;" ::: "memory");
    asm volatile("barrier.cluster.wait.aligned;"   ::: "memory");

    // ---------------- time loop ----------------
    for (int t = 0; t < Tn; t++) {
        const int pb = (t + 3) & 3;    // buffer holding out(t-1)
        const int cb = t & 3;          // buffer receiving out(t)
        const float dtR = DTc * s.Rs[t];
        const float* __restrict__ op = s.o[pb];

        // prefetch x(t) early (L2-resident after warmup)
        float4 xv = make_float4(0.f, 0.f, 0.f, 0.f);
        if (l < 28) xv = *reinterpret_cast<const float4*>(&x[(t * Bn + b) * INn + lk]);

        // --- phase 1: fused wa update (deferred from t-1) + logits (28 warps);
        //     readout of t-1 (warps 30/31) ---
        if (w < 28) {
            const float hbg = ((t > 0) ? DTc * s.Rs[t - 1] : 0.f) * kfb * attn_g;
            const int h0 = q * 128;
            float* __restrict__ war  = &s.wa[g * Hn];
            const float* __restrict__ abr = &s.awba[g * Hn];
            float p = 0.f;
            #pragma unroll
            for (int it = 0; it < 4; it++) {
                const int h = h0 + it * 32 + l;
                const float ov = op[h];
                const float hedge = (h < En) ? ov : 0.f;
                float v = fmaf(war[h], OMAWc, abr[h]);
                v = fmaf(hbg, hedge, v);
                v = fmaxf(v, 0.f);
                war[h] = v;
                const float osm = (h < EXn) ? ((h < En) ? ov : -ov) : 0.f;
                p = fmaf(v, osm, p);
            }
            p = warp_sum(p);
            if (l == 0) s.logits4[q][g] = p;
        } else if (t > 0 && (w == 31 || (w == 30 && rank == 0))) {
            const float* __restrict__ ew = (w == 31) ? s.effc : s.effv;
            const int ch = (w == 31) ? rank : 8;
            float p = 0.f;
            #pragma unroll 4
            for (int it = 0; it < 16; it++) {
                const int h = it * 32 + l;
                p = fmaf(ew[h], op[h], p);
            }
            p = warp_sum(p);
            if (l == 0) yout[((t - 1) * Bn + b) * 9 + ch] = p;
        }
        __syncthreads();

        // --- softmax replicated in every warp (constant-shift, no max pass) ---
        float gate;
        {
            const float L = (l < NGn)
                ? s.logits4[0][l] + s.logits4[1][l] + s.logits4[2][l]
                  + s.logits4[3][l] + s.battn[l] : 0.f;
            const float e = (l < NGn) ? __expf(L - 20.f) : 0.f;
            const float ssum = warp_sum(e);
            const float a = __fdividef(e, ssum);
            attn_g = __shfl_sync(0xffffffffu, a, g);
            gate   = __shfl_sync(0xffffffffu, a, l >> 2);
        }
        if (l < 28) { xv.x *= gate; xv.y *= gate; xv.z *= gate; xv.w *= gate; }

        // --- recurrent + input matvec (sign applied analytically on c4==3) ---
        float part[2] = {0.f, 0.f};
        #pragma unroll
        for (int c4 = 0; c4 < 4; c4++) {
            float4 ov = *reinterpret_cast<const float4*>(&op[c4 * 128 + lk]);
            if (c4 == 3) {   // sign boundary at j = 409 (j = 384 + lk + i)
                if (lk + 0 >= 25) ov.x = -ov.x;
                if (lk + 1 >= 25) ov.y = -ov.y;
                if (lk + 2 >= 25) ov.z = -ov.z;
                if (lk + 3 >= 25) ov.w = -ov.w;
            }
            #pragma unroll
            for (int r = 0; r < 2; r++) {
                part[r] = fmaf(wh[r][c4*4+0], ov.x, part[r]);
                part[r] = fmaf(wh[r][c4*4+1], ov.y, part[r]);
                part[r] = fmaf(wh[r][c4*4+2], ov.z, part[r]);
                part[r] = fmaf(wh[r][c4*4+3], ov.w, part[r]);
            }
        }
        if (l < 28) {
            #pragma unroll
            for (int r = 0; r < 2; r++) {
                const float4 wxv = *reinterpret_cast<const float4*>(
                    &s.wx[(rl0 + r) * INn + lk]);
                part[r] = fmaf(wxv.x, xv.x, part[r]);
                part[r] = fmaf(wxv.y, xv.y, part[r]);
                part[r] = fmaf(wxv.z, xv.z, part[r]);
                part[r] = fmaf(wxv.w, xv.w, part[r]);
            }
        }

        // --- reduce, state update, out(t) ---
        float base[2];
        #pragma unroll
        for (int r = 0; r < 2; r++) {
            float tot = warp_sum(part[r]);
            const float4 rd = *reinterpret_cast<const float4*>(&s.rowdat[(rl0 + r) * 4]);
            const float orow = op[row0 + r];
            const float osrow = (row0 + r >= En) ? -orow : orow;
            tot = tot - rd.z * osrow + rd.x;        // remove diagonal, add bias
            state[r] = fmaf(AXc, tot, OMAXc * state[r]);
        }
        float tv;
        {
            float st = (l == 0) ? state[0] : state[1];
            tv = tanh_relu_fast(st);
            base[0] = dtR * __shfl_sync(0xffffffffu, tv, 0);
            base[1] = dtR * __shfl_sync(0xffffffffu, tv, 1);
        }

        // --- push out(t) to all 8 cluster CTAs (lane l<16: row l&1, rank l>>1) ---
        if (l < 16) {
            const int rr  = l & 1;
            const int trk = l >> 1;
            const float val = __shfl_sync(0x0000ffffu, tv, rr);
            st_clu(smem_u32(&s.o[cb][row0 + rr]), trk, val);
        }

        asm volatile("barrier.cluster.arrive.aligned;" ::: "memory");

        // --- plastic wh/wx updates (hidden behind the cluster barrier) ---
        // safe to reload op after arrive: peers overwrite buffer pb only at
        // their step t+3 push, which requires our arrive(t+2).
        #pragma unroll
        for (int c4 = 0; c4 < 3; c4++) {        // uniform column-half tiles
            const float4 ov = *reinterpret_cast<const float4*>(&op[c4 * 128 + lk]);
            #pragma unroll
            for (int r = 0; r < 2; r++) {
                const float cAr = base[r] * ((row0 + r >= En) ? k10 : k00);
                const float4 ab = *reinterpret_cast<const float4*>(
                    &s.awbh[(rl0 + r) * Hn + c4 * 128 + lk]);
                float v0 = fmaf(wh[r][c4*4+0], OMAWc, ab.x); v0 = fmaf(cAr, ov.x, v0);
                float v1 = fmaf(wh[r][c4*4+1], OMAWc, ab.y); v1 = fmaf(cAr, ov.y, v1);
                float v2 = fmaf(wh[r][c4*4+2], OMAWc, ab.z); v2 = fmaf(cAr, ov.z, v2);
                float v3 = fmaf(wh[r][c4*4+3], OMAWc, ab.w); v3 = fmaf(cAr, ov.w, v3);
                wh[r][c4*4+0] = fmaxf(v0, 0.f);
                wh[r][c4*4+1] = fmaxf(v1, 0.f);
                wh[r][c4*4+2] = fmaxf(v2, 0.f);
                wh[r][c4*4+3] = fmaxf(v3, 0.f);
            }
        }
        {   // c4 == 3: mixed column-half tile (boundary at lk + i >= 25)
            const float4 ov = *reinterpret_cast<const float4*>(&op[384 + lk]);
            #pragma unroll
            for (int r = 0; r < 2; r++) {
                const bool rhbr = (row0 + r >= En);
                const float cAr = base[r] * (rhbr ? k10 : k00);
                const float cBr = base[r] * (rhbr ? k11 : k01);
                const float4 ab = *reinterpret_cast<const float4*>(
                    &s.awbh[(rl0 + r) * Hn + 384 + lk]);
                const float c0 = (lk + 0 >= 25) ? cBr : cAr;
                const float c1 = (lk + 1 >= 25) ? cBr : cAr;
                const float c2 = (lk + 2 >= 25) ? cBr : cAr;
                const float c3 = (lk + 3 >= 25) ? cBr : cAr;
                float v0 = fmaf(wh[r][12], OMAWc, ab.x); v0 = fmaf(c0, ov.x, v0);
                float v1 = fmaf(wh[r][13], OMAWc, ab.y); v1 = fmaf(c1, ov.y, v1);
                float v2 = fmaf(wh[r][14], OMAWc, ab.z); v2 = fmaf(c2, ov.z, v2);
                float v3 = fmaf(wh[r][15], OMAWc, ab.w); v3 = fmaf(c3, ov.w, v3);
                wh[r][12] = fmaxf(v0, 0.f);
                wh[r][13] = fmaxf(v1, 0.f);
                wh[r][14] = fmaxf(v2, 0.f);
                wh[r][15] = fmaxf(v3, 0.f);
            }
        }
        // diagonal shadow (lane 0 only; visible to next step via its __syncthreads)
        if (l == 0) {
            #pragma unroll
            for (int r = 0; r < 2; r++) {
                const bool rhbr = (row0 + r >= En);
                const float cd = base[r] * (rhbr ? k11 : k00);
                const float awbd = s.rowdat[(rl0 + r) * 4 + 1];
                const float wdv  = s.rowdat[(rl0 + r) * 4 + 2];
                float v = fmaf(wdv, OMAWc, awbd);
                v = fmaf(cd, op[row0 + r], v);
                s.rowdat[(rl0 + r) * 4 + 2] = fmaxf(v, 0.f);
            }
        }
        if (l < 28) {
            #pragma unroll
            for (int r = 0; r < 2; r++) {
                const float4 wxv = *reinterpret_cast<const float4*>(
                    &s.wx[(rl0 + r) * INn + lk]);
                const float4 ab = *reinterpret_cast<const float4*>(
                    &s.awbx[(rl0 + r) * INn + lk]);
                const float cX = base[r] * ((row0 + r >= En) ? kinBt : kinAt);
                float v0 = fmaf(wxv.x, OMAWc, ab.x); v0 = fmaf(cX, xv.x, v0);
                float v1 = fmaf(wxv.y, OMAWc, ab.y); v1 = fmaf(cX, xv.y, v1);
                float v2 = fmaf(wxv.z, OMAWc, ab.z); v2 = fmaf(cX, xv.z, v2);
                float v3 = fmaf(wxv.w, OMAWc, ab.w); v3 = fmaf(cX, xv.w, v3);
                *reinterpret_cast<float4*>(&s.wx[(rl0 + r) * INn + lk]) =
                    make_float4(fmaxf(v0, 0.f), fmaxf(v1, 0.f),
                                fmaxf(v2, 0.f), fmaxf(v3, 0.f));
            }
        }

        asm volatile("barrier.cluster.wait.aligned;" ::: "memory");
    }

    // --- final readout for t = Tn-1 (out(31) sits in buffer (Tn-1)&3 = 3) ---
    if (w == 31 || (w == 30 && rank == 0)) {
        const float* __restrict__ ew = (w == 31) ? s.effc : s.effv;
        const int ch = (w == 31) ? rank : 8;
        float p = 0.f;
        #pragma unroll 4
        for (int it = 0; it < 16; it++) {
            const int h = it * 32 + l;
            p = fmaf(ew[h], s.o[3][h], p);
        }
        p = warp_sum(p);
        if (l == 0) yout[((Tn - 1) * Bn + b) * 9 + ch] = p;
    }
}

extern "C" void kernel_launch(void* const* d_in, const int* in_sizes, int n_in,
                              void* d_out, int out_size) {
    (void)in_sizes; (void)n_in; (void)out_size;
    const size_t smem = sizeof(SM);
    cudaFuncSetAttribute(rnn_kernel, cudaFuncAttributeMaxDynamicSharedMemorySize, (int)smem);
    rnn_kernel<<<Bn * 8, NT, smem>>>(
        (const float*)d_in[0], (const float*)d_in[1], (const float*)d_in[2],
        (const float*)d_in[3], (const float*)d_in[4], (const float*)d_in[5],
        (const float*)d_in[6], (const float*)d_in[7], (const float*)d_in[8],
        (const float*)d_in[9], (float*)d_out);
}

// round 9
// speedup vs baseline: 1.0099x; 1.0099x over previous
#include <cuda_runtime.h>
#include <cstdint>

#define Bn   16
#define Tn   32
#define INn  112
#define Hn   512
#define NGn  7
#define En   409      // int(0.8*512)
#define EXn  410      // H - round(0.2*512)
#define AWc   0.02f
#define OMAWc 0.98f
#define AXc   0.2f
#define OMAXc 0.8f
#define DTc   0.02f
#define NT   1024

struct __align__(16) SM {
    float awbh[64 * Hn];    // alpha_w * relu(w_h2h) rows of this CTA   131072 B
    float wx[64 * INn];     // plastic input weights (thread-private)    28672 B
    float awbx[64 * INn];   // alpha_w * relu(w_x2h)                     28672 B
    float wa[NGn * Hn];     // plastic attn weights                      14336 B
    float awba[NGn * Hn];   //                                           14336 B
    float effc[Hn];         // relu(w_h2o[rank]) * exist                  2048 B
    float effv[Hn];         // relu(w_h2v) * exist                        2048 B
    float o[4][Hn];         // out(tau) lives in o[tau & 3]               8192 B
    float rowdat[64 * 4];   // per local row: {bh, awbd, wd, pad}         1024 B
    float logits4[4][8];
    float battn[8];
    float kap[24];
    float Rs[Tn];
};

__device__ __forceinline__ float warp_sum(float v) {
    v += __shfl_xor_sync(0xffffffffu, v, 16);
    v += __shfl_xor_sync(0xffffffffu, v, 8);
    v += __shfl_xor_sync(0xffffffffu, v, 4);
    v += __shfl_xor_sync(0xffffffffu, v, 2);
    v += __shfl_xor_sync(0xffffffffu, v, 1);
    return v;
}
__device__ __forceinline__ unsigned int smem_u32(const void* p) {
    unsigned int a;
    asm("{ .reg .u64 t; cvta.to.shared.u64 t, %1; cvt.u32.u64 %0, t; }" : "=r"(a) : "l"(p));
    return a;
}
__device__ __forceinline__ void st_clu(unsigned int laddr, int rank, float v) {
    unsigned int ra;
    asm volatile("mapa.shared::cluster.u32 %0, %1, %2;" : "=r"(ra) : "r"(laddr), "r"(rank));
    asm volatile("st.shared::cluster.f32 [%0], %1;" :: "r"(ra), "f"(v) : "memory");
}
// tanh(relu(x)) with fast exp/div; exact saturation beyond 15
__device__ __forceinline__ float tanh_relu_fast(float x) {
    float xr = fminf(fmaxf(x, 0.f), 15.f);
    float e2 = __expf(2.f * xr);
    return __fdividef(e2 - 1.f, e2 + 1.f);
}

__global__ void __launch_bounds__(NT, 1) __cluster_dims__(8, 1, 1)
rnn_kernel(const float* __restrict__ x, const float* __restrict__ R,
           const float* __restrict__ w_x2h, const float* __restrict__ w_h2h,
           const float* __restrict__ b_h2h, const float* __restrict__ w_attn,
           const float* __restrict__ b_attn, const float* __restrict__ w_h2o,
           const float* __restrict__ w_h2v, const float* __restrict__ kappa,
           float* __restrict__ yout)
{
    extern __shared__ __align__(16) char smraw[];
    SM& s = *reinterpret_cast<SM*>(smraw);

    const int tid  = threadIdx.x;
    const int w    = tid >> 5;          // 0..31
    const int l    = tid & 31;
    const int rank = blockIdx.x & 7;
    const int b    = blockIdx.x >> 3;
    const int rl0  = w * 2;             // local row base (0..62), 2 rows per warp
    const int row0 = rank * 64 + rl0;   // global row base
    const int lk   = l * 4;             // column base within a 128-block
    const int g    = w >> 2;            // attention group for warps < 28
    const int q    = w & 3;             // quarter-H slice for phase 1

    // ---------------- init ----------------
    if (tid < 24) s.kap[tid]   = (tid < 21)  ? kappa[tid]  : 0.f;
    if (tid < 8)  s.battn[tid] = (tid < NGn) ? b_attn[tid] : 0.f;
    if (tid < Tn) s.Rs[tid]    = R[tid * Bn + b];
    if (tid < Hn) {
        s.o[3][tid] = 0.f;              // out(-1) = 0
        s.effc[tid] = (tid < EXn) ? fmaxf(w_h2o[rank * Hn + tid], 0.f) : 0.f;
        s.effv[tid] = (tid < EXn) ? fmaxf(w_h2v[tid], 0.f) : 0.f;
    }
    for (int i = tid; i < NGn * Hn; i += NT) {
        float v = fmaxf(w_attn[i], 0.f);
        s.wa[i] = v; s.awba[i] = AWc * v;
    }
    if (l < 2) {
        const int row = row0 + l;
        const float dv = fmaxf(w_h2h[row * Hn + row], 0.f);
        s.rowdat[(rl0 + l) * 4 + 0] = b_h2h[row];
        s.rowdat[(rl0 + l) * 4 + 1] = AWc * dv;
        s.rowdat[(rl0 + l) * 4 + 2] = dv;
        s.rowdat[(rl0 + l) * 4 + 3] = 0.f;
    }

    float wh[2][16];
    #pragma unroll
    for (int r = 0; r < 2; r++) {
        const int row = row0 + r;
        #pragma unroll
        for (int c4 = 0; c4 < 4; c4++) {
            const int j0 = c4 * 128 + lk;
            float4 v = *reinterpret_cast<const float4*>(&w_h2h[row * Hn + j0]);
            v.x = fmaxf(v.x, 0.f); v.y = fmaxf(v.y, 0.f);
            v.z = fmaxf(v.z, 0.f); v.w = fmaxf(v.w, 0.f);
            wh[r][c4*4+0] = v.x; wh[r][c4*4+1] = v.y;
            wh[r][c4*4+2] = v.z; wh[r][c4*4+3] = v.w;
            *reinterpret_cast<float4*>(&s.awbh[(rl0 + r) * Hn + j0]) =
                make_float4(AWc*v.x, AWc*v.y, AWc*v.z, AWc*v.w);
        }
        if (l < 28) {
            float4 v = *reinterpret_cast<const float4*>(&w_x2h[row * INn + lk]);
            v.x = fmaxf(v.x, 0.f); v.y = fmaxf(v.y, 0.f);
            v.z = fmaxf(v.z, 0.f); v.w = fmaxf(v.w, 0.f);
            *reinterpret_cast<float4*>(&s.wx[(rl0 + r) * INn + lk]) = v;
            *reinterpret_cast<float4*>(&s.awbx[(rl0 + r) * INn + lk]) =
                make_float4(AWc*v.x, AWc*v.y, AWc*v.z, AWc*v.w);
        }
    }

    float state0 = 0.f, state1 = 0.f;
    float attn_g = 0.f;

    __syncthreads();
    asm volatile("barrier.cluster.arrive.aligned;" ::: "memory");
    asm volatile("barrier.cluster.wait.aligned;"   ::: "memory");

    // ---------------- time loop ----------------
    for (int t = 0; t < Tn; t++) {
        const int pb = (t + 3) & 3;    // buffer holding out(t-1)
        const int cb = t & 3;          // buffer receiving out(t)
        const float* __restrict__ op = s.o[pb];
        const float* __restrict__ xrow = &x[(t * Bn + b) * INn];

        // --- phase 1: fused wa update (deferred from t-1) + logits (28 warps);
        //     readout of t-1 (warps 30/31) ---
        if (w < 28) {
            const float hbg = ((t > 0) ? DTc * s.Rs[t - 1] : 0.f)
                              * s.kap[18 + g / 3] * attn_g;
            const int h0 = q * 128;
            float* __restrict__ war  = &s.wa[g * Hn];
            const float* __restrict__ abr = &s.awba[g * Hn];
            float p = 0.f;
            #pragma unroll
            for (int it = 0; it < 4; it++) {
                const int h = h0 + it * 32 + l;
                const float ov = op[h];
                const float hedge = (h < En) ? ov : 0.f;
                float v = fmaf(war[h], OMAWc, abr[h]);
                v = fmaf(hbg, hedge, v);
                v = fmaxf(v, 0.f);
                war[h] = v;
                const float osm = (h < EXn) ? ((h < En) ? ov : -ov) : 0.f;
                p = fmaf(v, osm, p);
            }
            p = warp_sum(p);
            if (l == 0) s.logits4[q][g] = p;
        } else if (t > 0 && (w == 31 || (w == 30 && rank == 0))) {
            const float* __restrict__ ew = (w == 31) ? s.effc : s.effv;
            const int ch = (w == 31) ? rank : 8;
            float p = 0.f;
            #pragma unroll 4
            for (int it = 0; it < 16; it++) {
                const int h = it * 32 + l;
                p = fmaf(ew[h], op[h], p);
            }
            p = warp_sum(p);
            if (l == 0) yout[((t - 1) * Bn + b) * 9 + ch] = p;
        }
        __syncthreads();

        // --- softmax replicated in every warp (constant-shift, no max pass) ---
        float gate;
        {
            const float L = (l < NGn)
                ? s.logits4[0][l] + s.logits4[1][l] + s.logits4[2][l]
                  + s.logits4[3][l] + s.battn[l] : 0.f;
            const float e = (l < NGn) ? __expf(L - 20.f) : 0.f;
            const float ssum = warp_sum(e);
            const float a = __fdividef(e, ssum);
            attn_g = __shfl_sync(0xffffffffu, a, g);
            gate   = __shfl_sync(0xffffffffu, a, l >> 2);
        }

        // --- recurrent + input matvec (sign applied analytically on c4==3) ---
        float part0 = 0.f, part1 = 0.f;
        #pragma unroll
        for (int c4 = 0; c4 < 4; c4++) {
            float4 ov = *reinterpret_cast<const float4*>(&op[c4 * 128 + lk]);
            if (c4 == 3) {   // sign boundary at j = 409 (j = 384 + lk + i)
                if (lk + 0 >= 25) ov.x = -ov.x;
                if (lk + 1 >= 25) ov.y = -ov.y;
                if (lk + 2 >= 25) ov.z = -ov.z;
                if (lk + 3 >= 25) ov.w = -ov.w;
            }
            part0 = fmaf(wh[0][c4*4+0], ov.x, part0);
            part0 = fmaf(wh[0][c4*4+1], ov.y, part0);
            part0 = fmaf(wh[0][c4*4+2], ov.z, part0);
            part0 = fmaf(wh[0][c4*4+3], ov.w, part0);
            part1 = fmaf(wh[1][c4*4+0], ov.x, part1);
            part1 = fmaf(wh[1][c4*4+1], ov.y, part1);
            part1 = fmaf(wh[1][c4*4+2], ov.z, part1);
            part1 = fmaf(wh[1][c4*4+3], ov.w, part1);
        }
        if (l < 28) {
            float4 xv = *reinterpret_cast<const float4*>(&xrow[lk]);
            xv.x *= gate; xv.y *= gate; xv.z *= gate; xv.w *= gate;
            const float4 w0 = *reinterpret_cast<const float4*>(&s.wx[(rl0 + 0) * INn + lk]);
            const float4 w1 = *reinterpret_cast<const float4*>(&s.wx[(rl0 + 1) * INn + lk]);
            part0 = fmaf(w0.x, xv.x, part0); part0 = fmaf(w0.y, xv.y, part0);
            part0 = fmaf(w0.z, xv.z, part0); part0 = fmaf(w0.w, xv.w, part0);
            part1 = fmaf(w1.x, xv.x, part1); part1 = fmaf(w1.y, xv.y, part1);
            part1 = fmaf(w1.z, xv.z, part1); part1 = fmaf(w1.w, xv.w, part1);
        }

        // --- reduce, state update, out(t) ---
        {
            float tot0 = warp_sum(part0);
            float tot1 = warp_sum(part1);
            const float4 rd0 = *reinterpret_cast<const float4*>(&s.rowdat[(rl0 + 0) * 4]);
            const float4 rd1 = *reinterpret_cast<const float4*>(&s.rowdat[(rl0 + 1) * 4]);
            const float or0 = op[row0 + 0];
            const float or1 = op[row0 + 1];
            tot0 = tot0 - rd0.z * ((row0 + 0 >= En) ? -or0 : or0) + rd0.x;
            tot1 = tot1 - rd1.z * ((row0 + 1 >= En) ? -or1 : or1) + rd1.x;
            state0 = fmaf(AXc, tot0, OMAXc * state0);
            state1 = fmaf(AXc, tot1, OMAXc * state1);
        }
        float base0, base1;
        {
            const float dtR = DTc * s.Rs[t];
            const float tv = tanh_relu_fast((l == 0) ? state0 : state1);
            base0 = dtR * __shfl_sync(0xffffffffu, tv, 0);
            base1 = dtR * __shfl_sync(0xffffffffu, tv, 1);
            // push out(t) to all 8 cluster CTAs (lane l<16: row l&1, rank l>>1)
            if (l < 16) {
                const float val = __shfl_sync(0x0000ffffu, tv, l & 1);
                st_clu(smem_u32(&s.o[cb][row0 + (l & 1)]), l >> 1, val);
            }
        }

        asm volatile("barrier.cluster.arrive.aligned;" ::: "memory");

        // --- plastic wh/wx updates (hidden behind the cluster barrier) ---
        // safe to reload op after arrive: peers overwrite buffer pb only at
        // their step t+3 push, which requires our arrive(t+2).
        {
            const float cA0 = base0 * ((row0 + 0 >= En) ? s.kap[2] : s.kap[0]);
            const float cA1 = base1 * ((row0 + 1 >= En) ? s.kap[2] : s.kap[0]);
            #pragma unroll
            for (int c4 = 0; c4 < 3; c4++) {    // uniform column-half tiles
                const float4 ov = *reinterpret_cast<const float4*>(&op[c4 * 128 + lk]);
                const float4 a0 = *reinterpret_cast<const float4*>(
                    &s.awbh[(rl0 + 0) * Hn + c4 * 128 + lk]);
                const float4 a1 = *reinterpret_cast<const float4*>(
                    &s.awbh[(rl0 + 1) * Hn + c4 * 128 + lk]);
                float v0, v1, v2, v3;
                v0 = fmaf(wh[0][c4*4+0], OMAWc, a0.x); v0 = fmaf(cA0, ov.x, v0);
                v1 = fmaf(wh[0][c4*4+1], OMAWc, a0.y); v1 = fmaf(cA0, ov.y, v1);
                v2 = fmaf(wh[0][c4*4+2], OMAWc, a0.z); v2 = fmaf(cA0, ov.z, v2);
                v3 = fmaf(wh[0][c4*4+3], OMAWc, a0.w); v3 = fmaf(cA0, ov.w, v3);
                wh[0][c4*4+0] = fmaxf(v0, 0.f); wh[0][c4*4+1] = fmaxf(v1, 0.f);
                wh[0][c4*4+2] = fmaxf(v2, 0.f); wh[0][c4*4+3] = fmaxf(v3, 0.f);
                v0 = fmaf(wh[1][c4*4+0], OMAWc, a1.x); v0 = fmaf(cA1, ov.x, v0);
                v1 = fmaf(wh[1][c4*4+1], OMAWc, a1.y); v1 = fmaf(cA1, ov.y, v1);
                v2 = fmaf(wh[1][c4*4+2], OMAWc, a1.z); v2 = fmaf(cA1, ov.z, v2);
                v3 = fmaf(wh[1][c4*4+3], OMAWc, a1.w); v3 = fmaf(cA1, ov.w, v3);
                wh[1][c4*4+0] = fmaxf(v0, 0.f); wh[1][c4*4+1] = fmaxf(v1, 0.f);
                wh[1][c4*4+2] = fmaxf(v2, 0.f); wh[1][c4*4+3] = fmaxf(v3, 0.f);
            }
            {   // c4 == 3: mixed column-half tile (boundary at lk + i >= 25)
                const float4 ov = *reinterpret_cast<const float4*>(&op[384 + lk]);
                const float cB0 = base0 * ((row0 + 0 >= En) ? s.kap[3] : s.kap[1]);
                const float cB1 = base1 * ((row0 + 1 >= En) ? s.kap[3] : s.kap[1]);
                const float4 a0 = *reinterpret_cast<const float4*>(
                    &s.awbh[(rl0 + 0) * Hn + 384 + lk]);
                const float4 a1 = *reinterpret_cast<const float4*>(
                    &s.awbh[(rl0 + 1) * Hn + 384 + lk]);
                const bool b0 = (lk + 0 >= 25), b1c = (lk + 1 >= 25);
                const bool b2 = (lk + 2 >= 25), b3 = (lk + 3 >= 25);
                float v0, v1, v2, v3;
                v0 = fmaf(wh[0][12], OMAWc, a0.x); v0 = fmaf(b0 ? cB0 : cA0, ov.x, v0);
                v1 = fmaf(wh[0][13], OMAWc, a0.y); v1 = fmaf(b1c ? cB0 : cA0, ov.y, v1);
                v2 = fmaf(wh[0][14], OMAWc, a0.z); v2 = fmaf(b2 ? cB0 : cA0, ov.z, v2);
                v3 = fmaf(wh[0][15], OMAWc, a0.w); v3 = fmaf(b3 ? cB0 : cA0, ov.w, v3);
                wh[0][12] = fmaxf(v0, 0.f); wh[0][13] = fmaxf(v1, 0.f);
                wh[0][14] = fmaxf(v2, 0.f); wh[0][15] = fmaxf(v3, 0.f);
                v0 = fmaf(wh[1][12], OMAWc, a1.x); v0 = fmaf(b0 ? cB1 : cA1, ov.x, v0);
                v1 = fmaf(wh[1][13], OMAWc, a1.y); v1 = fmaf(b1c ? cB1 : cA1, ov.y, v1);
                v2 = fmaf(wh[1][14], OMAWc, a1.z); v2 = fmaf(b2 ? cB1 : cA1, ov.z, v2);
                v3 = fmaf(wh[1][15], OMAWc, a1.w); v3 = fmaf(b3 ? cB1 : cA1, ov.w, v3);
                wh[1][12] = fmaxf(v0, 0.f); wh[1][13] = fmaxf(v1, 0.f);
                wh[1][14] = fmaxf(v2, 0.f); wh[1][15] = fmaxf(v3, 0.f);
            }
            // diagonal shadow (lane 0 only; visible next step via its __syncthreads)
            if (l == 0) {
                const float cd0 = base0 * ((row0 + 0 >= En) ? s.kap[3] : s.kap[0]);
                const float cd1 = base1 * ((row0 + 1 >= En) ? s.kap[3] : s.kap[0]);
                float v0 = fmaf(s.rowdat[(rl0 + 0) * 4 + 2], OMAWc,
                                s.rowdat[(rl0 + 0) * 4 + 1]);
                float v1 = fmaf(s.rowdat[(rl0 + 1) * 4 + 2], OMAWc,
                                s.rowdat[(rl0 + 1) * 4 + 1]);
                v0 = fmaf(cd0, op[row0 + 0], v0);
                v1 = fmaf(cd1, op[row0 + 1], v1);
                s.rowdat[(rl0 + 0) * 4 + 2] = fmaxf(v0, 0.f);
                s.rowdat[(rl0 + 1) * 4 + 2] = fmaxf(v1, 0.f);
            }
            if (l < 28) {
                float4 xv = *reinterpret_cast<const float4*>(&xrow[lk]);  // L1 hit
                xv.x *= gate; xv.y *= gate; xv.z *= gate; xv.w *= gate;
                const float cX0 = base0 *
                    ((row0 + 0 >= En) ? s.kap[5 + 2 * (l >> 2)] : s.kap[4 + 2 * (l >> 2)]);
                const float cX1 = base1 *
                    ((row0 + 1 >= En) ? s.kap[5 + 2 * (l >> 2)] : s.kap[4 + 2 * (l >> 2)]);
                const float4 w0 = *reinterpret_cast<const float4*>(&s.wx[(rl0 + 0) * INn + lk]);
                const float4 w1 = *reinterpret_cast<const float4*>(&s.wx[(rl0 + 1) * INn + lk]);
                const float4 ab0 = *reinterpret_cast<const float4*>(&s.awbx[(rl0 + 0) * INn + lk]);
                const float4 ab1 = *reinterpret_cast<const float4*>(&s.awbx[(rl0 + 1) * INn + lk]);
                float v0, v1, v2, v3;
                v0 = fmaf(w0.x, OMAWc, ab0.x); v0 = fmaf(cX0, xv.x, v0);
                v1 = fmaf(w0.y, OMAWc, ab0.y); v1 = fmaf(cX0, xv.y, v1);
                v2 = fmaf(w0.z, OMAWc, ab0.z); v2 = fmaf(cX0, xv.z, v2);
                v3 = fmaf(w0.w, OMAWc, ab0.w); v3 = fmaf(cX0, xv.w, v3);
                *reinterpret_cast<float4*>(&s.wx[(rl0 + 0) * INn + lk]) =
                    make_float4(fmaxf(v0, 0.f), fmaxf(v1, 0.f), fmaxf(v2, 0.f), fmaxf(v3, 0.f));
                v0 = fmaf(w1.x, OMAWc, ab1.x); v0 = fmaf(cX1, xv.x, v0);
                v1 = fmaf(w1.y, OMAWc, ab1.y); v1 = fmaf(cX1, xv.y, v1);
                v2 = fmaf(w1.z, OMAWc, ab1.z); v2 = fmaf(cX1, xv.z, v2);
                v3 = fmaf(w1.w, OMAWc, ab1.w); v3 = fmaf(cX1, xv.w, v3);
                *reinterpret_cast<float4*>(&s.wx[(rl0 + 1) * INn + lk]) =
                    make_float4(fmaxf(v0, 0.f), fmaxf(v1, 0.f), fmaxf(v2, 0.f), fmaxf(v3, 0.f));
            }
        }

        asm volatile("barrier.cluster.wait.aligned;" ::: "memory");
    }

    // --- final readout for t = Tn-1 (out(31) sits in buffer (Tn-1)&3 = 3) ---
    if (w == 31 || (w == 30 && rank == 0)) {
        const float* __restrict__ ew = (w == 31) ? s.effc : s.effv;
        const int ch = (w == 31) ? rank : 8;
        float p = 0.f;
        #pragma unroll 4
        for (int it = 0; it < 16; it++) {
            const int h = it * 32 + l;
            p = fmaf(ew[h], s.o[3][h], p);
        }
        p = warp_sum(p);
        if (l == 0) yout[((Tn - 1) * Bn + b) * 9 + ch] = p;
    }
}

extern "C" void kernel_launch(void* const* d_in, const int* in_sizes, int n_in,
                              void* d_out, int out_size) {
    (void)in_sizes; (void)n_in; (void)out_size;
    const size_t smem = sizeof(SM);
    cudaFuncSetAttribute(rnn_kernel, cudaFuncAttributeMaxDynamicSharedMemorySize, (int)smem);
    rnn_kernel<<<Bn * 8, NT, smem>>>(
        (const float*)d_in[0], (const float*)d_in[1], (const float*)d_in[2],
        (const float*)d_in[3], (const float*)d_in[4], (const float*)d_in[5],
        (const float*)d_in[6], (const float*)d_in[7], (const float*)d_in[8],
        (const float*)d_in[9], (float*)d_out);
}

// round 10
// speedup vs baseline: 1.5398x; 1.5247x over previous
#include <cuda_runtime.h>
#include <cstdint>

#define Bn   16
#define Tn   32
#define INn  112
#define Hn   512
#define NGn  7
#define En   409      // int(0.8*512)
#define EXn  410      // H - round(0.2*512)
#define AWc   0.02f
#define OMAWc 0.98f
#define AXc   0.2f
#define OMAXc 0.8f
#define DTc   0.02f

struct __align__(16) SM {
    float awbh[64 * Hn];    // alpha_w * relu(w_h2h) rows of this CTA   131072 B
    float wx[64 * INn];     // plastic input weights (thread-private)    28672 B
    float awbx[64 * INn];   // alpha_w * relu(w_x2h)                     28672 B
    float wa[NGn * 64];     // plastic attn weights, THIS CTA's columns   1792 B
    float awba[NGn * 64];   //                                            1792 B
    float effc[Hn];         // relu(w_h2o[rank]) * exist                  2048 B
    float effv[Hn];         // relu(w_h2v) * exist                        2048 B
    float o[4][Hn];         // out(tau) lives in o[tau & 3]               8192 B
    float rowdat[64 * 4];   // per local row: {bh, awbd, wd, pad}         1024 B
    float plog[2][8][8];    // partial logits [parity][src_rank][group]    512 B
    float battn[8];
    float Rs[Tn];
};

__device__ __forceinline__ float warp_sum(float v) {
    v += __shfl_xor_sync(0xffffffffu, v, 16);
    v += __shfl_xor_sync(0xffffffffu, v, 8);
    v += __shfl_xor_sync(0xffffffffu, v, 4);
    v += __shfl_xor_sync(0xffffffffu, v, 2);
    v += __shfl_xor_sync(0xffffffffu, v, 1);
    return v;
}
__device__ __forceinline__ unsigned int smem_u32(const void* p) {
    unsigned int a;
    asm("{ .reg .u64 t; cvta.to.shared.u64 t, %1; cvt.u32.u64 %0, t; }" : "=r"(a) : "l"(p));
    return a;
}
__device__ __forceinline__ void st_clu(unsigned int laddr, int rank, float v) {
    unsigned int ra;
    asm volatile("mapa.shared::cluster.u32 %0, %1, %2;" : "=r"(ra) : "r"(laddr), "r"(rank));
    asm volatile("st.shared::cluster.f32 [%0], %1;" :: "r"(ra), "f"(v) : "memory");
}
// tanh(relu(x)) with fast exp/div; exact saturation beyond 15
__device__ __forceinline__ float tanh_relu_fast(float x) {
    float xr = fminf(fmaxf(x, 0.f), 15.f);
    float e2 = __expf(2.f * xr);
    return __fdividef(e2 - 1.f, e2 + 1.f);
}

__global__ void __launch_bounds__(512, 1) __cluster_dims__(8, 1, 1)
rnn_kernel(const float* __restrict__ x, const float* __restrict__ R,
           const float* __restrict__ w_x2h, const float* __restrict__ w_h2h,
           const float* __restrict__ b_h2h, const float* __restrict__ w_attn,
           const float* __restrict__ b_attn, const float* __restrict__ w_h2o,
           const float* __restrict__ w_h2v, const float* __restrict__ kappa,
           float* __restrict__ yout)
{
    extern __shared__ __align__(16) char smraw[];
    SM& s = *reinterpret_cast<SM*>(smraw);

    const int tid  = threadIdx.x;
    const int w    = tid >> 5;
    const int l    = tid & 31;
    const int rank = blockIdx.x & 7;
    const int b    = blockIdx.x >> 3;
    const int rl0  = w * 4;            // local row base in CTA (0..60)
    const int row0 = rank * 64 + rl0;  // global row base
    const int lk   = l * 4;            // column base within a 128-block
    const int g    = (w < NGn) ? w : 0;   // attention group for wa warps

    // ---------------- init ----------------
    if (tid < 8)   s.battn[tid] = (tid < NGn) ? b_attn[tid] : 0.f;
    if (tid < Tn)  s.Rs[tid]    = R[tid * Bn + b];
    if (tid < 128) reinterpret_cast<float*>(s.plog)[tid] = 0.f;
    s.o[3][tid] = 0.f;                 // out(-1) = 0
    if (tid < NGn * 64) {              // this CTA's wa columns
        const int gg = tid >> 6, col = tid & 63;
        const float v = fmaxf(w_attn[gg * Hn + rank * 64 + col], 0.f);
        s.wa[tid] = v; s.awba[tid] = AWc * v;
    }
    s.effc[tid] = (tid < EXn) ? fmaxf(w_h2o[rank * Hn + tid], 0.f) : 0.f;
    s.effv[tid] = (tid < EXn) ? fmaxf(w_h2v[tid], 0.f) : 0.f;
    if (l < 4) {
        const int row = row0 + l;
        const float dv = fmaxf(w_h2h[row * Hn + row], 0.f);
        s.rowdat[(rl0 + l) * 4 + 0] = b_h2h[row];
        s.rowdat[(rl0 + l) * 4 + 1] = AWc * dv;
        s.rowdat[(rl0 + l) * 4 + 2] = dv;
        s.rowdat[(rl0 + l) * 4 + 3] = 0.f;
    }

    // uniform kappa scalars
    const float k00 = kappa[0], k01 = kappa[1], k10 = kappa[2], k11 = kappa[3];
    const float kinAt = kappa[4 + 2 * (l >> 2)];
    const float kinBt = kappa[5 + 2 * (l >> 2)];
    const float kfb = kappa[18 + g / 3];

    float wh[4][16];
    #pragma unroll
    for (int r = 0; r < 4; r++) {
        const int row = row0 + r;
        #pragma unroll
        for (int c4 = 0; c4 < 4; c4++) {
            const int j0 = c4 * 128 + lk;
            float4 v = *reinterpret_cast<const float4*>(&w_h2h[row * Hn + j0]);
            v.x = fmaxf(v.x, 0.f); v.y = fmaxf(v.y, 0.f);
            v.z = fmaxf(v.z, 0.f); v.w = fmaxf(v.w, 0.f);
            wh[r][c4*4+0] = v.x; wh[r][c4*4+1] = v.y;
            wh[r][c4*4+2] = v.z; wh[r][c4*4+3] = v.w;
            *reinterpret_cast<float4*>(&s.awbh[(rl0 + r) * Hn + j0]) =
                make_float4(AWc*v.x, AWc*v.y, AWc*v.z, AWc*v.w);
        }
        if (l < 28) {
            float4 v = *reinterpret_cast<const float4*>(&w_x2h[row * INn + lk]);
            v.x = fmaxf(v.x, 0.f); v.y = fmaxf(v.y, 0.f);
            v.z = fmaxf(v.z, 0.f); v.w = fmaxf(v.w, 0.f);
            *reinterpret_cast<float4*>(&s.wx[(rl0 + r) * INn + lk]) = v;
            *reinterpret_cast<float4*>(&s.awbx[(rl0 + r) * INn + lk]) =
                make_float4(AWc*v.x, AWc*v.y, AWc*v.z, AWc*v.w);
        }
    }

    float state[4] = {0.f, 0.f, 0.f, 0.f};

    __syncthreads();
    asm volatile("barrier.cluster.arrive.aligned;" ::: "memory");
    asm volatile("barrier.cluster.wait.aligned;"   ::: "memory");

    // ---------------- time loop ----------------
    for (int t = 0; t < Tn; t++) {
        const int pb  = (t + 3) & 3;   // buffer holding out(t-1)
        const int cb  = t & 3;         // buffer receiving out(t)
        const int pp  = t & 1;         // plog parity for THIS step's softmax
        const float dtR = DTc * s.Rs[t];
        const float* __restrict__ op = s.o[pb];
        const float* __restrict__ xrow = &x[(t * Bn + b) * INn];

        // --- softmax from pre-aggregated partial logits (8 LDS per lane<7) ---
        float gate, attn_g;
        {
            float L = 0.f;
            if (l < NGn) {
                const float* __restrict__ pl = &s.plog[pp][0][l];
                L = ((pl[0] + pl[8]) + (pl[16] + pl[24]))
                  + ((pl[32] + pl[40]) + (pl[48] + pl[56])) + s.battn[l];
            }
            const float e = (l < NGn) ? __expf(L - 20.f) : 0.f;
            const float ssum = warp_sum(e);
            const float a = __fdividef(e, ssum);
            attn_g = __shfl_sync(0xffffffffu, a, g);
            gate   = __shfl_sync(0xffffffffu, a, l >> 2);
        }

        // --- recurrent + input matvec (sign applied analytically on c4==3) ---
        float part[4] = {0.f, 0.f, 0.f, 0.f};
        #pragma unroll
        for (int c4 = 0; c4 < 4; c4++) {
            float4 ov = *reinterpret_cast<const float4*>(&op[c4 * 128 + lk]);
            if (c4 == 3) {   // sign boundary at j = 409 (j = 384 + lk + i)
                if (lk + 0 >= 25) ov.x = -ov.x;
                if (lk + 1 >= 25) ov.y = -ov.y;
                if (lk + 2 >= 25) ov.z = -ov.z;
                if (lk + 3 >= 25) ov.w = -ov.w;
            }
            #pragma unroll
            for (int r = 0; r < 4; r++) {
                part[r] = fmaf(wh[r][c4*4+0], ov.x, part[r]);
                part[r] = fmaf(wh[r][c4*4+1], ov.y, part[r]);
                part[r] = fmaf(wh[r][c4*4+2], ov.z, part[r]);
                part[r] = fmaf(wh[r][c4*4+3], ov.w, part[r]);
            }
        }
        float4 xv = make_float4(0.f, 0.f, 0.f, 0.f);
        if (l < 28) {
            xv = *reinterpret_cast<const float4*>(&xrow[lk]);
            xv.x *= gate; xv.y *= gate; xv.z *= gate; xv.w *= gate;
            #pragma unroll
            for (int r = 0; r < 4; r++) {
                const float4 wxv = *reinterpret_cast<const float4*>(
                    &s.wx[(rl0 + r) * INn + lk]);
                part[r] = fmaf(wxv.x, xv.x, part[r]);
                part[r] = fmaf(wxv.y, xv.y, part[r]);
                part[r] = fmaf(wxv.z, xv.z, part[r]);
                part[r] = fmaf(wxv.w, xv.w, part[r]);
            }
        }

        // --- reduce, state update, out(t) ---
        float base[4];
        #pragma unroll
        for (int r = 0; r < 4; r++) {
            float tot = warp_sum(part[r]);
            const float4 rd = *reinterpret_cast<const float4*>(&s.rowdat[(rl0 + r) * 4]);
            const float orow = op[row0 + r];
            const float osrow = (row0 + r >= En) ? -orow : orow;
            tot = tot - rd.z * osrow + rd.x;        // remove diagonal, add bias
            state[r] = fmaf(AXc, tot, OMAXc * state[r]);
        }
        float tv;
        {
            float st = (l == 0) ? state[0] : (l == 1) ? state[1] : (l == 2) ? state[2] : state[3];
            tv = tanh_relu_fast(st);
            #pragma unroll
            for (int r = 0; r < 4; r++)
                base[r] = dtR * __shfl_sync(0xffffffffu, tv, r);
        }

        // --- push out(t) to all 8 cluster CTAs (lane l -> row l&3, rank l>>2),
        //     plus a plain STS for own rows (local visibility insurance) ---
        {
            const float val = __shfl_sync(0xffffffffu, tv, l & 3);
            st_clu(smem_u32(&s.o[cb][row0 + (l & 3)]), l >> 2, val);
            if (l < 4) s.o[cb][row0 + l] = __shfl_sync(0x0000000fu, tv, l);
        }
        __syncthreads();   // own 64 rows of out(t) visible to all warps

        // --- wa slice update + partial logits for step t+1 (warps 0-6);
        //     readout of t-1 (warps 14/15) ---
        if (w < NGn) {
            const float hbg = dtR * kfb * attn_g;
            const int h0 = rank * 64;
            float p = 0.f;
            #pragma unroll
            for (int c = 0; c < 2; c++) {
                const int col = c * 32 + l;
                const int h = h0 + col;
                const float ot = s.o[cb][h];
                const float hedge = (h < En) ? ot : 0.f;
                float v = fmaf(s.wa[g * 64 + col], OMAWc, s.awba[g * 64 + col]);
                v = fmaf(hbg, hedge, v);
                v = fmaxf(v, 0.f);
                s.wa[g * 64 + col] = v;
                const float osm = (h < EXn) ? ((h < En) ? ot : -ot) : 0.f;
                p = fmaf(v, osm, p);
            }
            p = warp_sum(p);
            if (l < 8) st_clu(smem_u32(&s.plog[pp ^ 1][rank][g]), l, p);
        } else if (t > 0 && (w == 15 || (w == 14 && rank == 0))) {
            const float* __restrict__ ew = (w == 15) ? s.effc : s.effv;
            const int ch = (w == 15) ? rank : 8;
            float p = 0.f;
            #pragma unroll 4
            for (int it = 0; it < 16; it++) {
                const int h = it * 32 + l;
                p = fmaf(ew[h], op[h], p);
            }
            p = warp_sum(p);
            if (l == 0) yout[((t - 1) * Bn + b) * 9 + ch] = p;
        }

        asm volatile("barrier.cluster.arrive.aligned;" ::: "memory");

        // --- plastic wh/wx updates (hidden behind the cluster barrier) ---
        // safe to reload op after arrive: peers overwrite buffer pb only at
        // their step t+3 push, which requires our arrive(t+2).
        #pragma unroll
        for (int c4 = 0; c4 < 3; c4++) {        // uniform column-half tiles
            const float4 ov = *reinterpret_cast<const float4*>(&op[c4 * 128 + lk]);
            #pragma unroll
            for (int r = 0; r < 4; r++) {
                const float cAr = base[r] * ((row0 + r >= En) ? k10 : k00);
                const float4 ab = *reinterpret_cast<const float4*>(
                    &s.awbh[(rl0 + r) * Hn + c4 * 128 + lk]);
                float v0 = fmaf(wh[r][c4*4+0], OMAWc, ab.x); v0 = fmaf(cAr, ov.x, v0);
                float v1 = fmaf(wh[r][c4*4+1], OMAWc, ab.y); v1 = fmaf(cAr, ov.y, v1);
                float v2 = fmaf(wh[r][c4*4+2], OMAWc, ab.z); v2 = fmaf(cAr, ov.z, v2);
                float v3 = fmaf(wh[r][c4*4+3], OMAWc, ab.w); v3 = fmaf(cAr, ov.w, v3);
                wh[r][c4*4+0] = fmaxf(v0, 0.f);
                wh[r][c4*4+1] = fmaxf(v1, 0.f);
                wh[r][c4*4+2] = fmaxf(v2, 0.f);
                wh[r][c4*4+3] = fmaxf(v3, 0.f);
            }
        }
        {   // c4 == 3: mixed column-half tile (boundary at lk + i >= 25)
            const float4 ov = *reinterpret_cast<const float4*>(&op[384 + lk]);
            #pragma unroll
            for (int r = 0; r < 4; r++) {
                const bool rhbr = (row0 + r >= En);
                const float cAr = base[r] * (rhbr ? k10 : k00);
                const float cBr = base[r] * (rhbr ? k11 : k01);
                const float4 ab = *reinterpret_cast<const float4*>(
                    &s.awbh[(rl0 + r) * Hn + 384 + lk]);
                const float c0 = (lk + 0 >= 25) ? cBr : cAr;
                const float c1 = (lk + 1 >= 25) ? cBr : cAr;
                const float c2 = (lk + 2 >= 25) ? cBr : cAr;
                const float c3 = (lk + 3 >= 25) ? cBr : cAr;
                float v0 = fmaf(wh[r][12], OMAWc, ab.x); v0 = fmaf(c0, ov.x, v0);
                float v1 = fmaf(wh[r][13], OMAWc, ab.y); v1 = fmaf(c1, ov.y, v1);
                float v2 = fmaf(wh[r][14], OMAWc, ab.z); v2 = fmaf(c2, ov.z, v2);
                float v3 = fmaf(wh[r][15], OMAWc, ab.w); v3 = fmaf(c3, ov.w, v3);
                wh[r][12] = fmaxf(v0, 0.f);
                wh[r][13] = fmaxf(v1, 0.f);
                wh[r][14] = fmaxf(v2, 0.f);
                wh[r][15] = fmaxf(v3, 0.f);
            }
        }
        // diagonal shadow (lane 0 only; visible next step via its __syncthreads)
        if (l == 0) {
            #pragma unroll
            for (int r = 0; r < 4; r++) {
                const bool rhbr = (row0 + r >= En);
                const float cd = base[r] * (rhbr ? k11 : k00);
                const float awbd = s.rowdat[(rl0 + r) * 4 + 1];
                const float wdv  = s.rowdat[(rl0 + r) * 4 + 2];
                float v = fmaf(wdv, OMAWc, awbd);
                v = fmaf(cd, op[row0 + r], v);
                s.rowdat[(rl0 + r) * 4 + 2] = fmaxf(v, 0.f);
            }
        }
        if (l < 28) {
            #pragma unroll
            for (int r = 0; r < 4; r++) {
                const float4 wxv = *reinterpret_cast<const float4*>(
                    &s.wx[(rl0 + r) * INn + lk]);
                const float4 ab = *reinterpret_cast<const float4*>(
                    &s.awbx[(rl0 + r) * INn + lk]);
                const float cX = base[r] * ((row0 + r >= En) ? kinBt : kinAt);
                float v0 = fmaf(wxv.x, OMAWc, ab.x); v0 = fmaf(cX, xv.x, v0);
                float v1 = fmaf(wxv.y, OMAWc, ab.y); v1 = fmaf(cX, xv.y, v1);
                float v2 = fmaf(wxv.z, OMAWc, ab.z); v2 = fmaf(cX, xv.z, v2);
                float v3 = fmaf(wxv.w, OMAWc, ab.w); v3 = fmaf(cX, xv.w, v3);
                *reinterpret_cast<float4*>(&s.wx[(rl0 + r) * INn + lk]) =
                    make_float4(fmaxf(v0, 0.f), fmaxf(v1, 0.f),
                                fmaxf(v2, 0.f), fmaxf(v3, 0.f));
            }
        }

        asm volatile("barrier.cluster.wait.aligned;" ::: "memory");
    }

    // --- final readout for t = Tn-1 (out(31) sits in buffer (Tn-1)&3 = 3) ---
    if (w == 15 || (w == 14 && rank == 0)) {
        const float* __restrict__ ew = (w == 15) ? s.effc : s.effv;
        const int ch = (w == 15) ? rank : 8;
        float p = 0.f;
        #pragma unroll 4
        for (int it = 0; it < 16; it++) {
            const int h = it * 32 + l;
            p = fmaf(ew[h], s.o[3][h], p);
        }
        p = warp_sum(p);
        if (l == 0) yout[((Tn - 1) * Bn + b) * 9 + ch] = p;
    }
}

extern "C" void kernel_launch(void* const* d_in, const int* in_sizes, int n_in,
                              void* d_out, int out_size) {
    (void)in_sizes; (void)n_in; (void)out_size;
    const size_t smem = sizeof(SM);
    cudaFuncSetAttribute(rnn_kernel, cudaFuncAttributeMaxDynamicSharedMemorySize, (int)smem);
    rnn_kernel<<<Bn * 8, 512, smem>>>(
        (const float*)d_in[0], (const float*)d_in[1], (const float*)d_in[2],
        (const float*)d_in[3], (const float*)d_in[4], (const float*)d_in[5],
        (const float*)d_in[6], (const float*)d_in[7], (const float*)d_in[8],
        (const float*)d_in[9], (float*)d_out);
}